// round 3
// baseline (speedup 1.0000x reference)
#include <cuda_runtime.h>
#include <cstdint>

// Problem dims (fixed by the reference)
#define T_STEPS 512
#define BATCH   256
#define DIN     128
#define DH      512
#define DOUT    128

// Persistent recurrence config: 8 row-blocks x 16 col-blocks of 32x32 tiles
#define NCTA        128
#define REC_THREADS 128

// -------------------- device scratch (no allocation allowed) --------------------
__device__ float    g_xproj[(size_t)T_STEPS * BATCH * DH];   // 256 MB
__device__ float    g_h[2][BATCH * DH];                      // ping-pong hidden state
__device__ unsigned g_bar[T_STEPS];                          // per-step barrier counters

// -------------------- reset (runs every replay: determinism) --------------------
__global__ void reset_kernel() {
    int idx    = blockIdx.x * blockDim.x + threadIdx.x;
    int stride = gridDim.x * blockDim.x;
    if (idx < T_STEPS) g_bar[idx] = 0u;
    for (int i = idx; i < BATCH * DH; i += stride) g_h[0][i] = 0.0f;
}

// -------------------- xproj = xs @ W1x  (M=131072, N=512, K=128) --------------------
// 64x64 tiles, 256 threads, 4x4 microtile. fp32, fully parallel.
#define XPROJ_SMEM_FLOATS (64 * 132 + 128 * 64)
__global__ void __launch_bounds__(256) xproj_kernel(const float* __restrict__ xs,
                                                    const float* __restrict__ W1x) {
    extern __shared__ float sm[];
    float* xs_sm = sm;              // [64][132] (pad 4 -> conflict-free a loads)
    float* w_sm  = sm + 64 * 132;   // [128][64]

    const int tid  = threadIdx.x;
    const int row0 = blockIdx.x * 64;   // over T*B = 131072 rows
    const int col0 = blockIdx.y * 64;   // over DH = 512 cols

    // Stage xs tile (64 x 128 floats)
#pragma unroll
    for (int i = 0; i < 8; i++) {
        int idx = tid + i * 256;
        int r = idx >> 5, c4 = idx & 31;
        float4 v = *reinterpret_cast<const float4*>(xs + (size_t)(row0 + r) * DIN + c4 * 4);
        *reinterpret_cast<float4*>(xs_sm + r * 132 + c4 * 4) = v;
    }
    // Stage W1x tile (128 x 64 floats)
#pragma unroll
    for (int i = 0; i < 8; i++) {
        int idx = tid + i * 256;
        int k = idx >> 4, j4 = idx & 15;
        float4 v = *reinterpret_cast<const float4*>(W1x + (size_t)k * DH + col0 + j4 * 4);
        *reinterpret_cast<float4*>(w_sm + k * 64 + j4 * 4) = v;
    }
    __syncthreads();

    const int tx = tid & 15;   // 16 col groups of 4
    const int ty = tid >> 4;   // 16 row groups of 4

    float acc[4][4];
#pragma unroll
    for (int i = 0; i < 4; i++)
#pragma unroll
        for (int j = 0; j < 4; j++) acc[i][j] = 0.0f;

    const float*  a0p = xs_sm + (ty * 4 + 0) * 132;
    const float*  a1p = xs_sm + (ty * 4 + 1) * 132;
    const float*  a2p = xs_sm + (ty * 4 + 2) * 132;
    const float*  a3p = xs_sm + (ty * 4 + 3) * 132;
    const float4* w4  = reinterpret_cast<const float4*>(w_sm);

#pragma unroll 8
    for (int k = 0; k < DIN; k++) {
        float  a0 = a0p[k], a1 = a1p[k], a2 = a2p[k], a3 = a3p[k];
        float4 w  = w4[k * 16 + tx];
        acc[0][0] += a0 * w.x; acc[0][1] += a0 * w.y; acc[0][2] += a0 * w.z; acc[0][3] += a0 * w.w;
        acc[1][0] += a1 * w.x; acc[1][1] += a1 * w.y; acc[1][2] += a1 * w.z; acc[1][3] += a1 * w.w;
        acc[2][0] += a2 * w.x; acc[2][1] += a2 * w.y; acc[2][2] += a2 * w.z; acc[2][3] += a2 * w.w;
        acc[3][0] += a3 * w.x; acc[3][1] += a3 * w.y; acc[3][2] += a3 * w.z; acc[3][3] += a3 * w.w;
    }

#pragma unroll
    for (int i = 0; i < 4; i++) {
        float4 o = make_float4(acc[i][0], acc[i][1], acc[i][2], acc[i][3]);
        *reinterpret_cast<float4*>(g_xproj + (size_t)(row0 + ty * 4 + i) * DH + col0 + tx * 4) = o;
    }
}

// -------------------- persistent recurrence --------------------
// 128 CTAs, one per 32x32 tile of h. W1h column block (512x32 = 64KB) SMEM-resident
// across all 512 steps. Per step: restage own 32 h-rows (L2 -> SMEM), GEMM, tanh,
// store, grid barrier.
#define REC_SMEM_FLOATS (DH * 32 + 32 * 516)
__global__ void __launch_bounds__(REC_THREADS, 1)
rec_kernel(const float* __restrict__ W1h, const float* __restrict__ b1p) {
    extern __shared__ float sm[];
    float* w_sm = sm;             // [512][32]
    float* h_sm = sm + DH * 32;   // [32][516]  (pad 4 -> conflict-free column reads)

    const int tid  = threadIdx.x;
    const int cb   = blockIdx.x & 15;   // 16 column blocks
    const int rb   = blockIdx.x >> 4;   // 8 row blocks
    const int col0 = cb * 32;
    const int row0 = rb * 32;
    const int tx   = tid & 7;           // 8 col groups of 4
    const int ty   = tid >> 3;          // 16 -> rows ty and ty+16

    // Prologue: load W1h[:, col0:col0+32] into SMEM, once.
#pragma unroll 8
    for (int i = 0; i < 32; i++) {
        int idx = tid + i * REC_THREADS;
        int k = idx >> 3, j4 = idx & 7;
        float4 v = *reinterpret_cast<const float4*>(W1h + (size_t)k * DH + col0 + j4 * 4);
        *reinterpret_cast<float4*>(w_sm + k * 32 + j4 * 4) = v;
    }
    const float bias = b1p[0];
    __syncthreads();

    const float*  hin   = g_h[0];
    float*        hout  = g_h[1];
    const float*  hr0   = h_sm + (size_t)ty * 516;
    const float*  hr1   = h_sm + (size_t)(ty + 16) * 516;
    const float4* w4    = reinterpret_cast<const float4*>(w_sm);

    for (int s = 0; s < T_STEPS; s++) {
        // Prefetch xproj init values (overlaps with h restage below)
        const float* xp = g_xproj + ((size_t)s * BATCH + row0) * DH + col0;
        float4 x0 = __ldcg(reinterpret_cast<const float4*>(xp + (size_t)ty * DH + tx * 4));
        float4 x1 = __ldcg(reinterpret_cast<const float4*>(xp + (size_t)(ty + 16) * DH + tx * 4));

        // Restage h tile (32 rows x 512) L2 -> SMEM. __ldcg: never serve stale L1.
#pragma unroll 8
        for (int i = 0; i < 32; i++) {
            int idx = tid + i * REC_THREADS;
            int r = idx >> 7, c4 = idx & 127;
            float4 v = __ldcg(reinterpret_cast<const float4*>(hin + (size_t)(row0 + r) * DH + c4 * 4));
            *reinterpret_cast<float4*>(h_sm + r * 516 + c4 * 4) = v;
        }
        __syncthreads();

        float a00 = x0.x + bias, a01 = x0.y + bias, a02 = x0.z + bias, a03 = x0.w + bias;
        float a10 = x1.x + bias, a11 = x1.y + bias, a12 = x1.z + bias, a13 = x1.w + bias;

#pragma unroll 8
        for (int k = 0; k < DH; k++) {
            float  h0 = hr0[k];
            float  h1 = hr1[k];
            float4 w  = w4[k * 8 + tx];
            a00 += h0 * w.x; a01 += h0 * w.y; a02 += h0 * w.z; a03 += h0 * w.w;
            a10 += h1 * w.x; a11 += h1 * w.y; a12 += h1 * w.z; a13 += h1 * w.w;
        }

        float4 o0 = make_float4(tanhf(a00), tanhf(a01), tanhf(a02), tanhf(a03));
        float4 o1 = make_float4(tanhf(a10), tanhf(a11), tanhf(a12), tanhf(a13));
        *reinterpret_cast<float4*>(hout + (size_t)(row0 + ty) * DH + col0 + tx * 4)      = o0;
        *reinterpret_cast<float4*>(hout + (size_t)(row0 + ty + 16) * DH + col0 + tx * 4) = o1;

        if (s < T_STEPS - 1) {
            __threadfence();            // release: publish hout before arrival
            __syncthreads();            // all threads of CTA released
            if (tid == 0) {
                atomicAdd(&g_bar[s], 1u);
                while (*((volatile unsigned*)&g_bar[s]) < (unsigned)NCTA) { }
            }
            __syncthreads();            // fan out barrier release within CTA
        }

        const float* tmp = hin; hin = hout; hout = const_cast<float*>(tmp);
    }
    // 512 steps (even): final h lives in g_h[0].
}

// -------------------- out = h_final @ W2 + b2 --------------------
__global__ void __launch_bounds__(128) out_kernel(const float* __restrict__ W2,
                                                  const float* __restrict__ b2p,
                                                  float* __restrict__ out) {
    __shared__ float hs[DH];
    const int b = blockIdx.x;
    const int o = threadIdx.x;
    for (int i = o; i < DH; i += 128) hs[i] = g_h[0][(size_t)b * DH + i];
    __syncthreads();
    float acc = b2p[0];
#pragma unroll 8
    for (int k = 0; k < DH; k++) acc += hs[k] * W2[(size_t)k * DOUT + o];
    out[(size_t)b * DOUT + o] = acc;
}

// -------------------- launch --------------------
extern "C" void kernel_launch(void* const* d_in, const int* in_sizes, int n_in,
                              void* d_out, int out_size) {
    const float* xs  = (const float*)d_in[0];
    const float* W1x = (const float*)d_in[1];
    const float* W1h = (const float*)d_in[2];
    const float* b1  = (const float*)d_in[3];
    const float* W2  = (const float*)d_in[4];
    const float* b2  = (const float*)d_in[5];
    float* out = (float*)d_out;

    (void)in_sizes; (void)n_in; (void)out_size;

    cudaFuncSetAttribute(xproj_kernel, cudaFuncAttributeMaxDynamicSharedMemorySize,
                         XPROJ_SMEM_FLOATS * (int)sizeof(float));
    cudaFuncSetAttribute(rec_kernel, cudaFuncAttributeMaxDynamicSharedMemorySize,
                         REC_SMEM_FLOATS * (int)sizeof(float));

    reset_kernel<<<128, 256>>>();
    xproj_kernel<<<dim3((T_STEPS * BATCH) / 64, DH / 64), 256,
                   XPROJ_SMEM_FLOATS * sizeof(float)>>>(xs, W1x);
    rec_kernel<<<NCTA, REC_THREADS, REC_SMEM_FLOATS * sizeof(float)>>>(W1h, b1);
    out_kernel<<<BATCH, 128>>>(W2, b2, out);
}